// round 1
// baseline (speedup 1.0000x reference)
#include <cuda_runtime.h>
#include <math_constants.h>

#define NN 50000
#define NE 800000
#define ET (NE + NN)          // edges + self loops
#define DIM 128
#define NL 3
#define NG 64
#define NEG 0.2f

// ---- scratch (device globals; no allocation allowed) ----
__device__ float g_h[NN * DIM];     // h = x @ W
__device__ float g_x[NN * DIM];     // layer output (relu(agg + b)) -> next input
__device__ float g_agg[NN * DIM];   // per-dst accumulation
__device__ float g_alpha[ET];       // alpha, then exp(alpha - m)
__device__ float g_ssrc[NN];
__device__ float g_sdst[NN];
__device__ float g_m[NN];
__device__ float g_ssum[NN];

__device__ __forceinline__ void atomicMaxFloat(float* addr, float val) {
    if (val >= 0.f) atomicMax((int*)addr, __float_as_int(val));
    else            atomicMin((unsigned int*)addr, __float_as_uint(val));
}

// ---- GEMM: H[N,128] = X[N,128] @ W[128,128] ----
// 32 rows x 128 cols per block, 256 threads, each thread 4 rows x 4 cols.
__global__ __launch_bounds__(256) void gemm_kernel(const float* __restrict__ Xin,
                                                   const float* __restrict__ W) {
    __shared__ float Wsh[64 * 128];   // 32 KB  (one 64-deep K chunk)
    __shared__ float xs[32][65];      // padded: conflict-free broadcast reads

    const float* X = Xin ? Xin : g_x;
    int row0 = blockIdx.x * 32;
    int cx = threadIdx.x & 31;        // column group: cols 4*cx..4*cx+3
    int ry = threadIdx.x >> 5;        // row group:   rows ry*4..ry*4+3

    float4 acc[4];
    #pragma unroll
    for (int r = 0; r < 4; r++) acc[r] = make_float4(0.f, 0.f, 0.f, 0.f);

    for (int c = 0; c < 2; c++) {
        // load W chunk (rows c*64..c*64+63, all 128 cols) -> contiguous copy
        const float4* Wg = (const float4*)(W + c * 64 * DIM);
        float4* Ws4 = (float4*)Wsh;
        #pragma unroll
        for (int i = 0; i < 8; i++) Ws4[threadIdx.x + 256 * i] = Wg[threadIdx.x + 256 * i];
        // load x tile: 32 rows x 64 k
        for (int idx = threadIdx.x; idx < 32 * 64; idx += 256) {
            int r = idx >> 6, k = idx & 63;
            int row = row0 + r;
            xs[r][k] = (row < NN) ? X[row * DIM + c * 64 + k] : 0.f;
        }
        __syncthreads();

        #pragma unroll 16
        for (int k = 0; k < 64; k++) {
            float4 w4 = *(const float4*)(&Wsh[k * DIM + 4 * cx]);
            #pragma unroll
            for (int r = 0; r < 4; r++) {
                float xv = xs[ry * 4 + r][k];
                acc[r].x += xv * w4.x;
                acc[r].y += xv * w4.y;
                acc[r].z += xv * w4.z;
                acc[r].w += xv * w4.w;
            }
        }
        __syncthreads();
    }
    #pragma unroll
    for (int r = 0; r < 4; r++) {
        int row = row0 + ry * 4 + r;
        if (row < NN) *(float4*)(&g_h[row * DIM + 4 * cx]) = acc[r];
    }
}

// ---- per-node prep: s_src/s_dst dots, init m/ssum, zero agg ----
__global__ __launch_bounds__(256) void node_prep(const float* __restrict__ asrc,
                                                 const float* __restrict__ adst) {
    int warp = (blockIdx.x * blockDim.x + threadIdx.x) >> 5;
    int lane = threadIdx.x & 31;
    if (warp >= NN) return;
    float4 h4 = *(const float4*)(&g_h[warp * DIM + 4 * lane]);
    float4 a4 = *(const float4*)(&asrc[4 * lane]);
    float4 b4 = *(const float4*)(&adst[4 * lane]);
    float s1 = h4.x * a4.x + h4.y * a4.y + h4.z * a4.z + h4.w * a4.w;
    float s2 = h4.x * b4.x + h4.y * b4.y + h4.z * b4.z + h4.w * b4.w;
    #pragma unroll
    for (int o = 16; o; o >>= 1) {
        s1 += __shfl_xor_sync(0xFFFFFFFFu, s1, o);
        s2 += __shfl_xor_sync(0xFFFFFFFFu, s2, o);
    }
    if (lane == 0) {
        g_ssrc[warp] = s1;
        g_sdst[warp] = s2;
        g_m[warp] = -CUDART_INF_F;
        g_ssum[warp] = 0.f;
    }
    *(float4*)(&g_agg[warp * DIM + 4 * lane]) = make_float4(0.f, 0.f, 0.f, 0.f);
}

// ---- edge pass 1: alpha = leaky_relu(s_src[s]+s_dst[d]); segment max ----
__global__ __launch_bounds__(256) void edge_alpha_max(const int* __restrict__ ei) {
    int e = blockIdx.x * blockDim.x + threadIdx.x;
    if (e >= ET) return;
    int s, d;
    if (e < NE) { s = ei[e]; d = ei[NE + e]; }
    else        { s = d = e - NE; }
    float t = g_ssrc[s] + g_sdst[d];
    float a = t > 0.f ? t : NEG * t;
    g_alpha[e] = a;
    atomicMaxFloat(&g_m[d], a);
}

// ---- edge pass 2: e = exp(alpha - m[d]); segment sum ----
__global__ __launch_bounds__(256) void edge_exp_sum(const int* __restrict__ ei) {
    int e = blockIdx.x * blockDim.x + threadIdx.x;
    if (e >= ET) return;
    int d = (e < NE) ? ei[NE + e] : (e - NE);
    float ex = __expf(g_alpha[e] - g_m[d]);
    g_alpha[e] = ex;
    atomicAdd(&g_ssum[d], ex);
}

// ---- edge pass 3: agg[d] += (e/sum) * h[s]; one warp per edge ----
__global__ __launch_bounds__(256) void aggregate(const int* __restrict__ ei) {
    int gw = (blockIdx.x * blockDim.x + threadIdx.x) >> 5;
    int lane = threadIdx.x & 31;
    if (gw >= ET) return;
    int s, d;
    if (gw < NE) { s = ei[gw]; d = ei[NE + gw]; }
    else         { s = d = gw - NE; }
    float w = g_alpha[gw] / (g_ssum[d] + 1e-16f);
    float4 h4 = *(const float4*)(&g_h[s * DIM + 4 * lane]);
    float* p = &g_agg[d * DIM + 4 * lane];
    asm volatile("red.global.add.v4.f32 [%0], {%1, %2, %3, %4};"
                 :: "l"(p), "f"(w * h4.x), "f"(w * h4.y), "f"(w * h4.z), "f"(w * h4.w)
                 : "memory");
}

// ---- x = relu(agg + b) ----
__global__ __launch_bounds__(256) void bias_relu(const float* __restrict__ b) {
    int i = blockIdx.x * blockDim.x + threadIdx.x;   // float4 index
    if (i >= NN * DIM / 4) return;
    float4 v = *(const float4*)(&g_agg[4 * i]);
    float4 b4 = *(const float4*)(&b[(i & 31) * 4]);
    v.x = fmaxf(v.x + b4.x, 0.f);
    v.y = fmaxf(v.y + b4.y, 0.f);
    v.z = fmaxf(v.z + b4.z, 0.f);
    v.w = fmaxf(v.w + b4.w, 0.f);
    *(float4*)(&g_x[4 * i]) = v;
}

// ---- final: y[g] = bf + sum_{i: batch[i]=g} dot(x[i], Wf) ----
__global__ void init_y(const float* __restrict__ bf, float* __restrict__ y) {
    if (threadIdx.x < NG) y[threadIdx.x] = bf[0];
}

__global__ __launch_bounds__(256) void pool_kernel(const int* __restrict__ batch,
                                                   const float* __restrict__ Wf,
                                                   float* __restrict__ y) {
    int warp = (blockIdx.x * blockDim.x + threadIdx.x) >> 5;
    int lane = threadIdx.x & 31;
    if (warp >= NN) return;
    float4 x4 = *(const float4*)(&g_x[warp * DIM + 4 * lane]);
    float4 w4 = *(const float4*)(&Wf[4 * lane]);
    float s = x4.x * w4.x + x4.y * w4.y + x4.z * w4.z + x4.w * w4.w;
    #pragma unroll
    for (int o = 16; o; o >>= 1) s += __shfl_xor_sync(0xFFFFFFFFu, s, o);
    if (lane == 0) atomicAdd(&y[batch[warp]], s);
}

extern "C" void kernel_launch(void* const* d_in, const int* in_sizes, int n_in,
                              void* d_out, int out_size) {
    const float* x     = (const float*)d_in[0];
    const int*   ei    = (const int*)  d_in[1];
    const int*   batch = (const int*)  d_in[2];
    const float* Ws    = (const float*)d_in[3];
    const float* asrc  = (const float*)d_in[4];
    const float* adst  = (const float*)d_in[5];
    const float* bias  = (const float*)d_in[6];
    const float* Wf    = (const float*)d_in[7];
    const float* bf    = (const float*)d_in[8];
    float* y = (float*)d_out;

    const int EDGE_BLKS = (ET + 255) / 256;          // 3321
    const int WARP_BLKS = (NN * 32 + 255) / 256;     // 6250
    const int AGG_BLKS  = (ET * 32 + 255) / 256;     // 106250

    for (int l = 0; l < NL; l++) {
        gemm_kernel<<<(NN + 31) / 32, 256>>>(l == 0 ? x : nullptr, Ws + l * DIM * DIM);
        node_prep<<<WARP_BLKS, 256>>>(asrc + l * DIM, adst + l * DIM);
        edge_alpha_max<<<EDGE_BLKS, 256>>>(ei);
        edge_exp_sum<<<EDGE_BLKS, 256>>>(ei);
        aggregate<<<AGG_BLKS, 256>>>(ei);
        bias_relu<<<(NN * DIM / 4 + 255) / 256, 256>>>(bias + l * DIM);
    }
    init_y<<<1, 64>>>(bf, y);
    pool_kernel<<<WARP_BLKS, 256>>>(batch, Wf, y);
}

// round 2
// speedup vs baseline: 1.5843x; 1.5843x over previous
#include <cuda_runtime.h>
#include <math_constants.h>

#define NN 50000
#define NE 800000
#define ET (NE + NN)          // edges + self loops
#define DIM 128
#define NL 3
#define NG 64
#define NEG 0.2f

// ---- scratch (device globals; no allocation allowed) ----
__device__ float g_h[NN * DIM];     // h = x @ W
__device__ float g_x[NN * DIM];     // layer output
__device__ float g_ssrc[NN];
__device__ float g_sdst[NN];
__device__ int   g_deg[NN];
__device__ int   g_rowptr[NN + 1];
__device__ int   g_cursor[NN];
__device__ int   g_csrc[ET];        // src node per edge, grouped by dst

// ================= CSR build (once per launch) =================
__global__ __launch_bounds__(256) void zero_deg() {
    int i = blockIdx.x * blockDim.x + threadIdx.x;
    if (i < NN) g_deg[i] = 0;
}

__global__ __launch_bounds__(256) void count_deg(const int* __restrict__ ei) {
    int e = blockIdx.x * blockDim.x + threadIdx.x;
    if (e >= ET) return;
    int d = (e < NE) ? ei[NE + e] : (e - NE);
    atomicAdd(&g_deg[d], 1);
}

// single-block scan: warp-shuffle scan per 1024-chunk, running carry
__global__ __launch_bounds__(1024) void scan_deg() {
    __shared__ int wsum[32];
    __shared__ int s_carry;
    int tid = threadIdx.x, lane = tid & 31, wid = tid >> 5;
    if (tid == 0) { s_carry = 0; g_rowptr[0] = 0; }
    __syncthreads();
    for (int base = 0; base < NN; base += 1024) {
        int i = base + tid;
        int v = (i < NN) ? g_deg[i] : 0;
        int x = v;
        #pragma unroll
        for (int off = 1; off < 32; off <<= 1) {
            int t = __shfl_up_sync(0xFFFFFFFFu, x, off);
            if (lane >= off) x += t;
        }
        if (lane == 31) wsum[wid] = x;
        __syncthreads();
        if (wid == 0) {
            int y = wsum[lane];
            #pragma unroll
            for (int off = 1; off < 32; off <<= 1) {
                int t = __shfl_up_sync(0xFFFFFFFFu, y, off);
                if (lane >= off) y += t;
            }
            wsum[lane] = y;
        }
        __syncthreads();
        int incl = x + (wid > 0 ? wsum[wid - 1] : 0) + s_carry;
        if (i < NN) { g_rowptr[i + 1] = incl; g_cursor[i] = incl - v; }
        __syncthreads();
        if (tid == 1023) s_carry = incl;
        __syncthreads();
    }
}

__global__ __launch_bounds__(256) void scatter_edges(const int* __restrict__ ei) {
    int e = blockIdx.x * blockDim.x + threadIdx.x;
    if (e >= ET) return;
    int s, d;
    if (e < NE) { s = ei[e]; d = ei[NE + e]; }
    else        { s = d = e - NE; }
    int pos = atomicAdd(&g_cursor[d], 1);
    g_csrc[pos] = s;
}

// ================= GEMM: H[N,128] = X[N,128] @ W[128,128] =================
__global__ __launch_bounds__(256) void gemm_kernel(const float* __restrict__ Xin,
                                                   const float* __restrict__ W) {
    __shared__ float Wsh[64 * 128];
    __shared__ float xs[32][65];

    const float* X = Xin ? Xin : g_x;
    int row0 = blockIdx.x * 32;
    int cx = threadIdx.x & 31;
    int ry = threadIdx.x >> 5;

    float4 acc[4];
    #pragma unroll
    for (int r = 0; r < 4; r++) acc[r] = make_float4(0.f, 0.f, 0.f, 0.f);

    for (int c = 0; c < 2; c++) {
        const float4* Wg = (const float4*)(W + c * 64 * DIM);
        float4* Ws4 = (float4*)Wsh;
        #pragma unroll
        for (int i = 0; i < 8; i++) Ws4[threadIdx.x + 256 * i] = Wg[threadIdx.x + 256 * i];
        for (int idx = threadIdx.x; idx < 32 * 64; idx += 256) {
            int r = idx >> 6, k = idx & 63;
            int row = row0 + r;
            xs[r][k] = (row < NN) ? X[row * DIM + c * 64 + k] : 0.f;
        }
        __syncthreads();

        #pragma unroll 16
        for (int k = 0; k < 64; k++) {
            float4 w4 = *(const float4*)(&Wsh[k * DIM + 4 * cx]);
            #pragma unroll
            for (int r = 0; r < 4; r++) {
                float xv = xs[ry * 4 + r][k];
                acc[r].x += xv * w4.x;
                acc[r].y += xv * w4.y;
                acc[r].z += xv * w4.z;
                acc[r].w += xv * w4.w;
            }
        }
        __syncthreads();
    }
    #pragma unroll
    for (int r = 0; r < 4; r++) {
        int row = row0 + ry * 4 + r;
        if (row < NN) *(float4*)(&g_h[row * DIM + 4 * cx]) = acc[r];
    }
}

// ---- per-node attention dots ----
__global__ __launch_bounds__(256) void node_prep(const float* __restrict__ asrc,
                                                 const float* __restrict__ adst) {
    int warp = (blockIdx.x * blockDim.x + threadIdx.x) >> 5;
    int lane = threadIdx.x & 31;
    if (warp >= NN) return;
    float4 h4 = *(const float4*)(&g_h[warp * DIM + 4 * lane]);
    float4 a4 = *(const float4*)(&asrc[4 * lane]);
    float4 b4 = *(const float4*)(&adst[4 * lane]);
    float s1 = h4.x * a4.x + h4.y * a4.y + h4.z * a4.z + h4.w * a4.w;
    float s2 = h4.x * b4.x + h4.y * b4.y + h4.z * b4.z + h4.w * b4.w;
    #pragma unroll
    for (int o = 16; o; o >>= 1) {
        s1 += __shfl_xor_sync(0xFFFFFFFFu, s1, o);
        s2 += __shfl_xor_sync(0xFFFFFFFFu, s2, o);
    }
    if (lane == 0) { g_ssrc[warp] = s1; g_sdst[warp] = s2; }
}

__device__ __forceinline__ float leaky(float t) { return t > 0.f ? t : NEG * t; }

// ---- fused per-dst softmax + gather-aggregate + bias + relu (+ pool) ----
__global__ __launch_bounds__(256) void gat_agg(const float* __restrict__ bias,
                                               int do_pool,
                                               const int* __restrict__ batch,
                                               const float* __restrict__ Wf,
                                               float* __restrict__ y) {
    int d = (blockIdx.x * blockDim.x + threadIdx.x) >> 5;
    int lane = threadIdx.x & 31;
    if (d >= NN) return;

    int beg = g_rowptr[d], end = g_rowptr[d + 1];
    float sdst = g_sdst[d];

    // pass 1: max
    float m = -CUDART_INF_F;
    for (int p = beg + lane; p < end; p += 32)
        m = fmaxf(m, leaky(g_ssrc[g_csrc[p]] + sdst));
    #pragma unroll
    for (int o = 16; o; o >>= 1) m = fmaxf(m, __shfl_xor_sync(0xFFFFFFFFu, m, o));

    // pass 2: exp-sum
    float sum = 0.f;
    for (int p = beg + lane; p < end; p += 32)
        sum += __expf(leaky(g_ssrc[g_csrc[p]] + sdst) - m);
    #pragma unroll
    for (int o = 16; o; o >>= 1) sum += __shfl_xor_sync(0xFFFFFFFFu, sum, o);
    float inv = 1.f / (sum + 1e-16f);

    // pass 3: weighted gather (unroll x2 for MLP)
    float4 acc = make_float4(0.f, 0.f, 0.f, 0.f);
    int p = beg;
    for (; p + 1 < end; p += 2) {
        int s0 = g_csrc[p], s1 = g_csrc[p + 1];
        float w0 = __expf(leaky(g_ssrc[s0] + sdst) - m) * inv;
        float w1 = __expf(leaky(g_ssrc[s1] + sdst) - m) * inv;
        float4 h0 = *(const float4*)(&g_h[s0 * DIM + 4 * lane]);
        float4 h1 = *(const float4*)(&g_h[s1 * DIM + 4 * lane]);
        acc.x += w0 * h0.x + w1 * h1.x;
        acc.y += w0 * h0.y + w1 * h1.y;
        acc.z += w0 * h0.z + w1 * h1.z;
        acc.w += w0 * h0.w + w1 * h1.w;
    }
    if (p < end) {
        int s0 = g_csrc[p];
        float w0 = __expf(leaky(g_ssrc[s0] + sdst) - m) * inv;
        float4 h0 = *(const float4*)(&g_h[s0 * DIM + 4 * lane]);
        acc.x += w0 * h0.x; acc.y += w0 * h0.y;
        acc.z += w0 * h0.z; acc.w += w0 * h0.w;
    }

    float4 b4 = *(const float4*)(&bias[4 * lane]);
    acc.x = fmaxf(acc.x + b4.x, 0.f);
    acc.y = fmaxf(acc.y + b4.y, 0.f);
    acc.z = fmaxf(acc.z + b4.z, 0.f);
    acc.w = fmaxf(acc.w + b4.w, 0.f);

    if (do_pool) {
        float4 w4 = *(const float4*)(&Wf[4 * lane]);
        float s = acc.x * w4.x + acc.y * w4.y + acc.z * w4.z + acc.w * w4.w;
        #pragma unroll
        for (int o = 16; o; o >>= 1) s += __shfl_xor_sync(0xFFFFFFFFu, s, o);
        if (lane == 0) atomicAdd(&y[batch[d]], s);
    } else {
        *(float4*)(&g_x[d * DIM + 4 * lane]) = acc;
    }
}

__global__ void init_y(const float* __restrict__ bf, float* __restrict__ y) {
    if (threadIdx.x < NG) y[threadIdx.x] = bf[0];
}

extern "C" void kernel_launch(void* const* d_in, const int* in_sizes, int n_in,
                              void* d_out, int out_size) {
    const float* x     = (const float*)d_in[0];
    const int*   ei    = (const int*)  d_in[1];
    const int*   batch = (const int*)  d_in[2];
    const float* Ws    = (const float*)d_in[3];
    const float* asrc  = (const float*)d_in[4];
    const float* adst  = (const float*)d_in[5];
    const float* bias  = (const float*)d_in[6];
    const float* Wf    = (const float*)d_in[7];
    const float* bf    = (const float*)d_in[8];
    float* y = (float*)d_out;

    const int EDGE_BLKS = (ET + 255) / 256;
    const int WARP_BLKS = (NN * 32 + 255) / 256;

    // CSR build
    zero_deg<<<(NN + 255) / 256, 256>>>();
    count_deg<<<EDGE_BLKS, 256>>>(ei);
    scan_deg<<<1, 1024>>>();
    scatter_edges<<<EDGE_BLKS, 256>>>(ei);
    init_y<<<1, 64>>>(bf, y);

    for (int l = 0; l < NL; l++) {
        gemm_kernel<<<(NN + 31) / 32, 256>>>(l == 0 ? x : nullptr, Ws + l * DIM * DIM);
        node_prep<<<WARP_BLKS, 256>>>(asrc + l * DIM, adst + l * DIM);
        gat_agg<<<WARP_BLKS, 256>>>(bias + l * DIM, l == NL - 1 ? 1 : 0, batch, Wf, y);
    }
}